// round 6
// baseline (speedup 1.0000x reference)
#include <cuda_runtime.h>
#include <cuda_fp16.h>
#include <math.h>

#define N 4096
#define LOG16   2.772588722239781f    // log(16)
#define LOG_CU  13.862943611198906f   // log(2^20)
#define F_SCALE 1048576.0f            // 2^20
#define NBLOCKS 256
#define NTHREADS 256
#define NITER 10
#define CPB 2048                      // columns per block (2-way split)
#define NST 4                         // stages per warp-stream (512 cols / 128)
#define STG_B 256                     // stage bytes per row (128 fp16 cols)
#define A_STRIDE 272                  // padded row stride (17*16B -> ldmatrix conflict-free)
#define WBUF (16 * A_STRIDE)          // 4352 B per stage buffer
#define V_STRIDE_H 2056               // halves per V row (4112 B, conflict-free B loads)
#define SMEM_V (8 * V_STRIDE_H * 2)   // 32896
#define SMEM_A_OFF SMEM_V
#define SMEM_RED_OFF (SMEM_V + 8 * 2 * WBUF)       // 32896 + 69632 = 102528
#define SMEM_TOTAL (SMEM_RED_OFF + 8 * 16 * 4 * 4) // 104576

// Scratch (allocation-free rule: __device__ globals)
__device__ __half g_K [(size_t)N * N];   // 16*exp(-C/eps), row-major
__device__ __half g_KT[(size_t)N * N];   // transpose
__device__ float  g_pu[2 * N * 4];       // u-direction partials [chunk][row][s]
__device__ float  g_pv[2 * N * 4];       // v-direction partials
__device__ unsigned long long g_count;   // grid-barrier generation counter

// ---------------------------------------------------------------------------
// Software grid barrier: monotonic generation counter (graph-replay safe)
// ---------------------------------------------------------------------------
__device__ __forceinline__ void grid_sync() {
    __syncthreads();
    if (threadIdx.x == 0) {
        unsigned long long gen;
        asm volatile("atom.add.release.gpu.u64 %0, [%1], 1;"
                     : "=l"(gen) : "l"(&g_count) : "memory");
        unsigned long long target =
            (gen / NBLOCKS + 1ull) * (unsigned long long)NBLOCKS;
        unsigned long long cur;
        do {
            asm volatile("ld.acquire.gpu.u64 %0, [%1];"
                         : "=l"(cur) : "l"(&g_count) : "memory");
        } while (cur < target);
    }
    __syncthreads();
}

// ---------------------------------------------------------------------------
// Precompute K = 16*exp(-C/eps) and its transpose
// ---------------------------------------------------------------------------
__global__ void exp_transpose_kernel(const float* __restrict__ C,
                                     const float* __restrict__ epsp) {
    __shared__ __half tile[32][33];
    const float inv_eps = 1.0f / *epsp;
    const int tx = threadIdx.x, ty = threadIdx.y;
    const int bx = blockIdx.x << 5, by = blockIdx.y << 5;

#pragma unroll
    for (int k = 0; k < 4; ++k) {
        int r = by + ty + (k << 3);
        float c = C[(size_t)r * N + bx + tx];
        __half h = __float2half_rn(__expf(LOG16 - c * inv_eps));
        g_K[(size_t)r * N + bx + tx] = h;
        tile[ty + (k << 3)][tx] = h;
    }
    __syncthreads();
#pragma unroll
    for (int k = 0; k < 4; ++k) {
        int m = bx + ty + (k << 3);
        g_KT[(size_t)m * N + by + tx] = tile[tx][ty + (k << 3)];
    }
}

// ---------------------------------------------------------------------------
// Persistent tensor-core Sinkhorn, warp-synchronous streaming.
// 256 blocks x 256 threads. Block = 32 rows x 2048 cols (blockIdx=rowTile*2+chunk).
// Warp w: rt=w>>2 (16 rows), q=w&3 (512-col k-slab). Each warp streams its slab
// through a PRIVATE double-buffered smem ring via cp.async (no block syncs).
// ---------------------------------------------------------------------------
__global__ void __launch_bounds__(NTHREADS, 2)
sinkhorn_persistent_kernel(const float* __restrict__ alpha,
                           const float* __restrict__ beta,
                           const float* __restrict__ epsp,
                           float* __restrict__ out) {
    extern __shared__ char smem[];
    __half* Vs  = (__half*)smem;
    float*  red = (float*)(smem + SMEM_RED_OFF);

    const int tid  = threadIdx.x;
    const int warp = tid >> 5;
    const int lane = tid & 31;
    const int rowT  = blockIdx.x >> 1;
    const int chunk = blockIdx.x & 1;
    const int row0  = rowT * 32;
    const int colBase = chunk * CPB;
    const int rt = warp >> 2;
    const int q  = warp & 3;

    const unsigned sA = (unsigned)__cvta_generic_to_shared(smem + SMEM_A_OFF);
    const unsigned sV = (unsigned)__cvta_generic_to_shared(Vs);

    // zero V rows 4..7 once (N-padding of the mma B operand)
    for (int i = tid; i < 4 * V_STRIDE_H; i += NTHREADS)
        Vs[4 * V_STRIDE_H + i] = __float2half_rn(0.f);

    // per-warp stream bases
    const unsigned wbase = sA + warp * (2 * WBUF);
    const unsigned dlane = wbase + (lane >> 1) * A_STRIDE + (lane & 1) * 128;

    // ldmatrix lane address within warp buffer (16x16 A tile per k-step)
    const int gg   = lane >> 3;
    const unsigned abase = wbase + ((gg & 1) * 8 + (lane & 7)) * A_STRIDE + (gg >> 1) * 16;
    // B fragment base: n = lane>>2, k-pair offset = (lane&3)*4 bytes
    const unsigned bbase = sV + (lane >> 2) * (V_STRIDE_H * 2) + (lane & 3) * 4;

    for (int it = 0; it < 2 * NITER; ++it) {
        const __half* M    = (it & 1) ? g_KT : g_K;
        float*        pout = (it & 1) ? g_pv : g_pu;

        // per-lane gmem source for this warp's 16-row x 512-col slab
        const char* gsrc = (const char*)M
            + (size_t)(row0 + 16 * rt + (lane >> 1)) * (N * 2)
            + (size_t)(colBase + 512 * q) * 2 + (lane & 1) * 128;

        // ---- prologue: stage 0 in flight before V staging ----
        {
            unsigned dst = dlane;
#pragma unroll
            for (int u = 0; u < 8; ++u)
                asm volatile("cp.async.cg.shared.global [%0], [%1], 16;"
                             :: "r"(dst + u * 16), "l"(gsrc + u * 16) : "memory");
            asm volatile("cp.async.commit_group;" ::: "memory");
        }

        // ---- stage V (fp16, [n][k], divide fused; F_SCALE keeps fp16 normal) ----
        if (it == 0) {
            const __half one = __float2half_rn(1.f);
            for (int i = tid; i < CPB; i += NTHREADS) {
                Vs[0 * V_STRIDE_H + i] = one;
                Vs[1 * V_STRIDE_H + i] = one;
                Vs[2 * V_STRIDE_H + i] = one;
                Vs[3 * V_STRIDE_H + i] = one;
            }
        } else {
            const float*  num  = (it & 1) ? alpha : beta;
            const float4* part = (const float4*)((it & 1) ? g_pu : g_pv);
            for (int i = tid; i < CPB; i += NTHREADS) {
                int col = colBase + i;
                float4 p0 = __ldcg(part + col);
                float4 p1 = __ldcg(part + N + col);
                Vs[0 * V_STRIDE_H + i] = __float2half_rn(
                    __fdividef(F_SCALE * __ldg(num + 0 * N + col), p0.x + p1.x));
                Vs[1 * V_STRIDE_H + i] = __float2half_rn(
                    __fdividef(F_SCALE * __ldg(num + 1 * N + col), p0.y + p1.y));
                Vs[2 * V_STRIDE_H + i] = __float2half_rn(
                    __fdividef(F_SCALE * __ldg(num + 2 * N + col), p0.z + p1.z));
                Vs[3 * V_STRIDE_H + i] = __float2half_rn(
                    __fdividef(F_SCALE * __ldg(num + 3 * N + col), p0.w + p1.w));
            }
        }
        __syncthreads();   // V ready for all warps

        float dA0 = 0.f, dA1 = 0.f, dA2 = 0.f, dA3 = 0.f;
        float dB0 = 0.f, dB1 = 0.f, dB2 = 0.f, dB3 = 0.f;

#pragma unroll
        for (int s = 0; s < NST; ++s) {
            if (s + 1 < NST) {
                const char* src = gsrc + (s + 1) * STG_B;
                unsigned dst = dlane + ((s + 1) & 1) * WBUF;
#pragma unroll
                for (int u = 0; u < 8; ++u)
                    asm volatile("cp.async.cg.shared.global [%0], [%1], 16;"
                                 :: "r"(dst + u * 16), "l"(src + u * 16) : "memory");
                asm volatile("cp.async.commit_group;" ::: "memory");
                asm volatile("cp.async.wait_group 1;" ::: "memory");
            } else {
                asm volatile("cp.async.wait_group 0;" ::: "memory");
            }
            __syncwarp();

            const unsigned abuf = abase + (s & 1) * WBUF;
            const int kk0 = 512 * q + 128 * s;
#pragma unroll
            for (int j = 0; j < 8; ++j) {
                unsigned a0, a1, a2, a3;
                asm volatile("ldmatrix.sync.aligned.m8n8.x4.shared.b16 {%0,%1,%2,%3}, [%4];"
                             : "=r"(a0), "=r"(a1), "=r"(a2), "=r"(a3)
                             : "r"(abuf + 32 * j));
                const int kk = kk0 + 16 * j;
                unsigned b0, b1;
                asm volatile("ld.shared.b32 %0, [%1];" : "=r"(b0) : "r"(bbase + kk * 2));
                asm volatile("ld.shared.b32 %0, [%1];" : "=r"(b1) : "r"(bbase + kk * 2 + 16));
                if (j & 1) {
                    asm volatile("mma.sync.aligned.m16n8k16.row.col.f32.f16.f16.f32 "
                                 "{%0,%1,%2,%3}, {%4,%5,%6,%7}, {%8,%9}, {%0,%1,%2,%3};"
                                 : "+f"(dB0), "+f"(dB1), "+f"(dB2), "+f"(dB3)
                                 : "r"(a0), "r"(a1), "r"(a2), "r"(a3), "r"(b0), "r"(b1));
                } else {
                    asm volatile("mma.sync.aligned.m16n8k16.row.col.f32.f16.f16.f32 "
                                 "{%0,%1,%2,%3}, {%4,%5,%6,%7}, {%8,%9}, {%0,%1,%2,%3};"
                                 : "+f"(dA0), "+f"(dA1), "+f"(dA2), "+f"(dA3)
                                 : "r"(a0), "r"(a1), "r"(a2), "r"(a3), "r"(b0), "r"(b1));
                }
            }
        }

        const float d0 = dA0 + dB0, d1 = dA1 + dB1;
        const float d2 = dA2 + dB2, d3 = dA3 + dB3;

        // ---- epilogue: C fragments (cols 0-3 useful) -> smem -> q-reduction ----
        if ((lane & 3) < 2) {
            const int c = 2 * (lane & 3);
            const int r = lane >> 2;
            red[(warp * 16 + r) * 4 + c]     = d0;
            red[(warp * 16 + r) * 4 + c + 1] = d1;
            red[(warp * 16 + r + 8) * 4 + c]     = d2;
            red[(warp * 16 + r + 8) * 4 + c + 1] = d3;
        }
        __syncthreads();
        if (tid < 128) {
            const int rt2 = tid >> 6, row = (tid >> 2) & 15, c = tid & 3;
            float v = red[((4 * rt2 + 0) * 16 + row) * 4 + c]
                    + red[((4 * rt2 + 1) * 16 + row) * 4 + c]
                    + red[((4 * rt2 + 2) * 16 + row) * 4 + c]
                    + red[((4 * rt2 + 3) * 16 + row) * 4 + c];
            __stcg(pout + (size_t)chunk * N * 4
                        + (size_t)(row0 + 16 * rt2 + row) * 4 + c, v);
        }
        grid_sync();
    }

    // ---- finalize:  f = eps*(log a - log(Kv_scaled) + log16)
    //                 g = eps*(log b - log(KTu_scaled) + log 2^20)
    int n = blockIdx.x * NTHREADS + tid;
    if (n < N) {
        const float eps = *epsp;
        const float4* pu = (const float4*)g_pu;
        const float4* pv = (const float4*)g_pv;
        float4 u0 = __ldcg(pu + n), u1 = __ldcg(pu + N + n);
        float4 v0 = __ldcg(pv + n), v1 = __ldcg(pv + N + n);
        out[0 * N + n] = eps * (logf(alpha[0 * N + n]) - logf(u0.x + u1.x) + LOG16);
        out[1 * N + n] = eps * (logf(alpha[1 * N + n]) - logf(u0.y + u1.y) + LOG16);
        out[2 * N + n] = eps * (logf(alpha[2 * N + n]) - logf(u0.z + u1.z) + LOG16);
        out[3 * N + n] = eps * (logf(alpha[3 * N + n]) - logf(u0.w + u1.w) + LOG16);
        float* og = out + 4 * N;
        og[0 * N + n] = eps * (logf(beta[0 * N + n]) - logf(v0.x + v1.x) + LOG_CU);
        og[1 * N + n] = eps * (logf(beta[1 * N + n]) - logf(v0.y + v1.y) + LOG_CU);
        og[2 * N + n] = eps * (logf(beta[2 * N + n]) - logf(v0.z + v1.z) + LOG_CU);
        og[3 * N + n] = eps * (logf(beta[3 * N + n]) - logf(v0.w + v1.w) + LOG_CU);
    }
}

// ---------------------------------------------------------------------------
extern "C" void kernel_launch(void* const* d_in, const int* in_sizes, int n_in,
                              void* d_out, int out_size) {
    const float* alpha = (const float*)d_in[0];
    const float* beta  = (const float*)d_in[1];
    const float* C     = (const float*)d_in[2];
    const float* eps   = (const float*)d_in[3];
    float* out = (float*)d_out;

    cudaFuncSetAttribute(sinkhorn_persistent_kernel,
                         cudaFuncAttributeMaxDynamicSharedMemorySize, SMEM_TOTAL);

    exp_transpose_kernel<<<dim3(128, 128), dim3(32, 8)>>>(C, eps);
    sinkhorn_persistent_kernel<<<NBLOCKS, NTHREADS, SMEM_TOTAL>>>(alpha, beta, eps, out);
}

// round 7
// speedup vs baseline: 1.7924x; 1.7924x over previous
#include <cuda_runtime.h>
#include <cuda_fp16.h>
#include <math.h>

#define N 4096
#define LOG16   2.772588722239781f    // log(16)
#define LOG_CU  13.862943611198906f   // log(2^20)
#define F_SCALE 1048576.0f            // 2^20
#define NBLOCKS 512
#define NTHREADS 256
#define NITER 10
#define CPB 2048                      // k-columns per block (2-way chunk split)
#define KT_PER_WARP 16                // 16 k-tiles (of 16 cols) per warp
#define V_STRIDE_H 2056               // halves per V row (4112 B, conflict-free B loads)
#define SMEM_V (8 * V_STRIDE_H * 2)   // 32896
#define SMEM_RED_OFF SMEM_V
#define SMEM_TOTAL (SMEM_RED_OFF + 8 * 16 * 4 * 4)   // 34944

// Scratch (allocation-free rule: __device__ globals).
// K matrices stored FRAGMENT-MAJOR: tile t=(rowTile*256+kTile) occupies
// 256 halves; lane l's uint4 at t*32+l = {a0,a1,a2,a3} of mma.m16n8k16.
__device__ __half g_K [(size_t)N * N];
__device__ __half g_KT[(size_t)N * N];
__device__ float  g_pu[2 * N * 4];       // u-direction partials [chunk][col][s]
__device__ float  g_pv[2 * N * 4];
__device__ unsigned long long g_count;   // grid-barrier generation counter

// ---------------------------------------------------------------------------
// Software grid barrier: monotonic generation counter (graph-replay safe)
// ---------------------------------------------------------------------------
__device__ __forceinline__ void grid_sync() {
    __syncthreads();
    if (threadIdx.x == 0) {
        unsigned long long gen;
        asm volatile("atom.add.release.gpu.u64 %0, [%1], 1;"
                     : "=l"(gen) : "l"(&g_count) : "memory");
        unsigned long long target =
            (gen / NBLOCKS + 1ull) * (unsigned long long)NBLOCKS;
        unsigned long long cur;
        do {
            asm volatile("ld.acquire.gpu.u64 %0, [%1];"
                         : "=l"(cur) : "l"(&g_count) : "memory");
        } while (cur < target);
    }
    __syncthreads();
}

__device__ __forceinline__ unsigned packh(__half lo, __half hi) {
    __half2 h = __halves2half2(lo, hi);
    return *reinterpret_cast<unsigned*>(&h);
}

// ---------------------------------------------------------------------------
// Fragment packer: 64x64 C region -> exp -> 16 K-tiles + 16 KT-tiles,
// written directly in m16n8k16 A-fragment layout (uint4 per lane).
// ---------------------------------------------------------------------------
__global__ void frag_pack_kernel(const float* __restrict__ C,
                                 const float* __restrict__ epsp) {
    __shared__ __half sE[64 * 72];           // 9216 B, padded stride 72
    const float inv_eps = 1.0f / *epsp;
    const int tid = threadIdx.x;
    const int bx = blockIdx.x << 6;          // C column base
    const int by = blockIdx.y << 6;          // C row base

    // load 64x64 C, exp, store halves to smem
    {
        const int r  = tid >> 2;
        const int c0 = (tid & 3) << 4;
        const float4* src = (const float4*)(C + (size_t)(by + r) * N + bx + c0);
        __half* dst = sE + r * 72 + c0;
#pragma unroll
        for (int q = 0; q < 4; ++q) {
            float4 f = src[q];
            dst[q * 4 + 0] = __float2half_rn(__expf(LOG16 - f.x * inv_eps));
            dst[q * 4 + 1] = __float2half_rn(__expf(LOG16 - f.y * inv_eps));
            dst[q * 4 + 2] = __float2half_rn(__expf(LOG16 - f.z * inv_eps));
            dst[q * 4 + 3] = __float2half_rn(__expf(LOG16 - f.w * inv_eps));
        }
    }
    __syncthreads();

    const int warp = tid >> 5, lane = tid & 31;
    const int rr = lane >> 2, cc = (lane & 3) << 1;

#pragma unroll
    for (int p = 0; p < 2; ++p) {
        const int t = warp * 2 + p;          // 0..15
        const int i = t >> 2, j = t & 3;

        // ---- K tile: rows = C rows, k = C cols ----
        {
            const __half* b = sE + (i * 16 + rr) * 72 + (j * 16 + cc);
            unsigned r0 = *(const unsigned*)(b);
            unsigned r1 = *(const unsigned*)(b + 8 * 72);
            unsigned r2 = *(const unsigned*)(b + 8);
            unsigned r3 = *(const unsigned*)(b + 8 * 72 + 8);
            size_t tileK = ((size_t)((by >> 4) + i) * (N / 16)) + (bx >> 4) + j;
            ((uint4*)g_K)[tileK * 32 + lane] = make_uint4(r0, r1, r2, r3);
        }
        // ---- KT tile: rows = C cols, k = C rows (transposed read) ----
        {
            const __half* b = sE + (j * 16 + cc) * 72 + (i * 16 + rr);
            unsigned r0 = packh(b[0],          b[72]);
            unsigned r1 = packh(b[8],          b[72 + 8]);
            unsigned r2 = packh(b[8 * 72],     b[9 * 72]);
            unsigned r3 = packh(b[8 * 72 + 8], b[9 * 72 + 8]);
            size_t tileT = ((size_t)((bx >> 4) + i) * (N / 16)) + (by >> 4) + j;
            ((uint4*)g_KT)[tileT * 32 + lane] = make_uint4(r0, r1, r2, r3);
        }
    }
}

// ---------------------------------------------------------------------------
// Persistent tensor-core Sinkhorn, fragment-direct loads.
// 512 blocks x 256 threads. Block = rowTile (16 rows) x 2048 cols
// (blockIdx = rowTile*2 + chunk). Warp w streams 16 contiguous fragment
// tiles: LDG.128 -> 2x LDS.32 (V) -> HMMA. No cp.async, no ldmatrix.
// ---------------------------------------------------------------------------
__global__ void __launch_bounds__(NTHREADS, 4)
sinkhorn_persistent_kernel(const float* __restrict__ alpha,
                           const float* __restrict__ beta,
                           const float* __restrict__ epsp,
                           float* __restrict__ out) {
    extern __shared__ char smem[];
    __half* Vs  = (__half*)smem;
    float*  red = (float*)(smem + SMEM_RED_OFF);

    const int tid  = threadIdx.x;
    const int warp = tid >> 5;
    const int lane = tid & 31;
    const int rt    = blockIdx.x >> 1;
    const int chunk = blockIdx.x & 1;
    const int row0  = rt * 16;
    const int colBase = chunk * CPB;

    const unsigned sV = (unsigned)__cvta_generic_to_shared(Vs);
    // B fragment base: n = lane>>2, k-pair offset = (lane&3)*4 bytes
    const unsigned bbase = sV + (lane >> 2) * (V_STRIDE_H * 2) + (lane & 3) * 4;
    const unsigned bwarp = bbase + (warp * KT_PER_WARP * 16) * 2;

    // zero V rows 4..7 once (N-padding of the B operand)
    for (int i = tid; i < 4 * V_STRIDE_H; i += NTHREADS)
        Vs[4 * V_STRIDE_H + i] = __float2half_rn(0.f);

    for (int it = 0; it < 2 * NITER; ++it) {
        const __half* M    = (it & 1) ? g_KT : g_K;
        float*        pout = (it & 1) ? g_pv : g_pu;

        // ---- stage V (fp16 [n][k], divide fused; F_SCALE keeps fp16 normal) ----
        if (it == 0) {
            const __half one = __float2half_rn(1.f);
            for (int i = tid; i < CPB; i += NTHREADS) {
                Vs[0 * V_STRIDE_H + i] = one;
                Vs[1 * V_STRIDE_H + i] = one;
                Vs[2 * V_STRIDE_H + i] = one;
                Vs[3 * V_STRIDE_H + i] = one;
            }
        } else {
            const float*  num  = (it & 1) ? alpha : beta;
            const float4* part = (const float4*)((it & 1) ? g_pu : g_pv);
            for (int i = tid; i < CPB; i += NTHREADS) {
                int col = colBase + i;
                float4 p0 = __ldcg(part + col);
                float4 p1 = __ldcg(part + N + col);
                Vs[0 * V_STRIDE_H + i] = __float2half_rn(
                    __fdividef(F_SCALE * __ldg(num + 0 * N + col), p0.x + p1.x));
                Vs[1 * V_STRIDE_H + i] = __float2half_rn(
                    __fdividef(F_SCALE * __ldg(num + 1 * N + col), p0.y + p1.y));
                Vs[2 * V_STRIDE_H + i] = __float2half_rn(
                    __fdividef(F_SCALE * __ldg(num + 2 * N + col), p0.z + p1.z));
                Vs[3 * V_STRIDE_H + i] = __float2half_rn(
                    __fdividef(F_SCALE * __ldg(num + 3 * N + col), p0.w + p1.w));
            }
        }
        __syncthreads();   // V ready

        // ---- mainloop: 16 fragment tiles, depth-4 load pipeline ----
        const uint4* frag = (const uint4*)M
            + ((size_t)rt * (N / 16) + chunk * 128 + warp * KT_PER_WARP) * 32 + lane;

        float dA0 = 0.f, dA1 = 0.f, dA2 = 0.f, dA3 = 0.f;
        float dB0 = 0.f, dB1 = 0.f, dB2 = 0.f, dB3 = 0.f;

        uint4 abuf[4];
#pragma unroll
        for (int q = 0; q < 4; ++q) abuf[q] = __ldcg(frag + q * 32);

#pragma unroll
        for (int g = 0; g < 4; ++g) {
            uint4 nbuf[4];
#pragma unroll
            for (int q = 0; q < 4; ++q)
                nbuf[q] = (g < 3) ? __ldcg(frag + ((g + 1) * 4 + q) * 32) : abuf[q];
#pragma unroll
            for (int q = 0; q < 4; ++q) {
                const int s = g * 4 + q;
                unsigned b0, b1;
                asm volatile("ld.shared.b32 %0, [%1];" : "=r"(b0) : "r"(bwarp + s * 32));
                asm volatile("ld.shared.b32 %0, [%1];" : "=r"(b1) : "r"(bwarp + s * 32 + 16));
                if (s & 1) {
                    asm volatile("mma.sync.aligned.m16n8k16.row.col.f32.f16.f16.f32 "
                                 "{%0,%1,%2,%3}, {%4,%5,%6,%7}, {%8,%9}, {%0,%1,%2,%3};"
                                 : "+f"(dB0), "+f"(dB1), "+f"(dB2), "+f"(dB3)
                                 : "r"(abuf[q].x), "r"(abuf[q].y), "r"(abuf[q].z), "r"(abuf[q].w),
                                   "r"(b0), "r"(b1));
                } else {
                    asm volatile("mma.sync.aligned.m16n8k16.row.col.f32.f16.f16.f32 "
                                 "{%0,%1,%2,%3}, {%4,%5,%6,%7}, {%8,%9}, {%0,%1,%2,%3};"
                                 : "+f"(dA0), "+f"(dA1), "+f"(dA2), "+f"(dA3)
                                 : "r"(abuf[q].x), "r"(abuf[q].y), "r"(abuf[q].z), "r"(abuf[q].w),
                                   "r"(b0), "r"(b1));
                }
            }
#pragma unroll
            for (int q = 0; q < 4; ++q) abuf[q] = nbuf[q];
        }

        const float d0 = dA0 + dB0, d1 = dA1 + dB1;
        const float d2 = dA2 + dB2, d3 = dA3 + dB3;

        // ---- epilogue: fragments (cols 0-3 useful) -> smem -> 8-warp reduce ----
        if ((lane & 3) < 2) {
            const int c = 2 * (lane & 3);
            const int r = lane >> 2;
            red[(warp * 16 + r) * 4 + c]         = d0;
            red[(warp * 16 + r) * 4 + c + 1]     = d1;
            red[(warp * 16 + r + 8) * 4 + c]     = d2;
            red[(warp * 16 + r + 8) * 4 + c + 1] = d3;
        }
        __syncthreads();
        if (tid < 64) {
            const int row = tid >> 2, c = tid & 3;
            float v = 0.f;
#pragma unroll
            for (int w = 0; w < 8; ++w)
                v += red[(w * 16 + row) * 4 + c];
            __stcg(pout + (size_t)chunk * N * 4 + (size_t)(row0 + row) * 4 + c, v);
        }
        grid_sync();
    }

    // ---- finalize:  f = eps*(log a - log p_u + log16)
    //                 g = eps*(log b - log p_v + log 2^20)
    int n = blockIdx.x * NTHREADS + tid;
    if (n < N) {
        const float eps = *epsp;
        const float4* pu = (const float4*)g_pu;
        const float4* pv = (const float4*)g_pv;
        float4 u0 = __ldcg(pu + n), u1 = __ldcg(pu + N + n);
        float4 v0 = __ldcg(pv + n), v1 = __ldcg(pv + N + n);
        out[0 * N + n] = eps * (logf(alpha[0 * N + n]) - logf(u0.x + u1.x) + LOG16);
        out[1 * N + n] = eps * (logf(alpha[1 * N + n]) - logf(u0.y + u1.y) + LOG16);
        out[2 * N + n] = eps * (logf(alpha[2 * N + n]) - logf(u0.z + u1.z) + LOG16);
        out[3 * N + n] = eps * (logf(alpha[3 * N + n]) - logf(u0.w + u1.w) + LOG16);
        float* og = out + 4 * N;
        og[0 * N + n] = eps * (logf(beta[0 * N + n]) - logf(v0.x + v1.x) + LOG_CU);
        og[1 * N + n] = eps * (logf(beta[1 * N + n]) - logf(v0.y + v1.y) + LOG_CU);
        og[2 * N + n] = eps * (logf(beta[2 * N + n]) - logf(v0.z + v1.z) + LOG_CU);
        og[3 * N + n] = eps * (logf(beta[3 * N + n]) - logf(v0.w + v1.w) + LOG_CU);
    }
}

// ---------------------------------------------------------------------------
extern "C" void kernel_launch(void* const* d_in, const int* in_sizes, int n_in,
                              void* d_out, int out_size) {
    const float* alpha = (const float*)d_in[0];
    const float* beta  = (const float*)d_in[1];
    const float* C     = (const float*)d_in[2];
    const float* eps   = (const float*)d_in[3];
    float* out = (float*)d_out;

    cudaFuncSetAttribute(sinkhorn_persistent_kernel,
                         cudaFuncAttributeMaxDynamicSharedMemorySize, SMEM_TOTAL);

    frag_pack_kernel<<<dim3(64, 64), 256>>>(C, eps);
    sinkhorn_persistent_kernel<<<NBLOCKS, NTHREADS, SMEM_TOTAL>>>(alpha, beta, eps, out);
}

// round 8
// speedup vs baseline: 2.6077x; 1.4548x over previous
#include <cuda_runtime.h>
#include <cuda_fp16.h>
#include <math.h>

#define N 4096
#define LOG16   2.772588722239781f    // log(16)
#define LOG_CU  13.862943611198906f   // log(2^20)
#define F_SCALE 1048576.0f            // 2^20
#define NBLOCKS 256
#define NTHREADS 256
#define NITER 10
#define NTILES 256                    // k-tiles per row (N/16)
#define TPW 32                        // tiles per warp (256/8)

// Scratch (allocation-free rule: __device__ globals).
// K matrices FRAGMENT-MAJOR: tile t = rt*256+kt occupies 32 uint4; lane l's
// uint4 at t*32+l = {a0..a3} of mma.m16n8k16. B vectors FRAGMENT-PACKED:
// tile t occupies 16 uint2 (lanes 0-15 only; n>=4 rows are implicit zeros).
__device__ __half g_K [(size_t)N * N];
__device__ __half g_KT[(size_t)N * N];
__device__ uint2  g_Bv[NTILES * 16];     // packed v (input of even passes)
__device__ uint2  g_Bu[NTILES * 16];     // packed u (input of odd passes)
__device__ float  g_pu[N * 4];           // final Kv sums  [row][s]
__device__ float  g_pv[N * 4];           // final KTu sums [row][s]
__device__ unsigned long long g_count;   // grid-barrier generation counter

// ---------------------------------------------------------------------------
// Software grid barrier: monotonic generation counter (graph-replay safe)
// ---------------------------------------------------------------------------
__device__ __forceinline__ void grid_sync() {
    __syncthreads();
    if (threadIdx.x == 0) {
        unsigned long long gen;
        asm volatile("atom.add.release.gpu.u64 %0, [%1], 1;"
                     : "=l"(gen) : "l"(&g_count) : "memory");
        unsigned long long target =
            (gen / NBLOCKS + 1ull) * (unsigned long long)NBLOCKS;
        unsigned long long cur;
        do {
            asm volatile("ld.acquire.gpu.u64 %0, [%1];"
                         : "=l"(cur) : "l"(&g_count) : "memory");
        } while (cur < target);
    }
    __syncthreads();
}

__device__ __forceinline__ unsigned packh(__half lo, __half hi) {
    __half2 h = __halves2half2(lo, hi);
    return *reinterpret_cast<unsigned*>(&h);
}

// ---------------------------------------------------------------------------
// Fragment packer: 64x64 C region -> exp -> 16 K-tiles + 16 KT-tiles,
// written directly in m16n8k16 A-fragment layout (uint4 per lane).
// ---------------------------------------------------------------------------
__global__ void frag_pack_kernel(const float* __restrict__ C,
                                 const float* __restrict__ epsp) {
    __shared__ __half sE[64 * 72];           // padded stride 72
    const float inv_eps = 1.0f / *epsp;
    const int tid = threadIdx.x;
    const int bx = blockIdx.x << 6;          // C column base
    const int by = blockIdx.y << 6;          // C row base

    {
        const int r  = tid >> 2;
        const int c0 = (tid & 3) << 4;
        const float4* src = (const float4*)(C + (size_t)(by + r) * N + bx + c0);
        __half* dst = sE + r * 72 + c0;
#pragma unroll
        for (int q = 0; q < 4; ++q) {
            float4 f = src[q];
            dst[q * 4 + 0] = __float2half_rn(__expf(LOG16 - f.x * inv_eps));
            dst[q * 4 + 1] = __float2half_rn(__expf(LOG16 - f.y * inv_eps));
            dst[q * 4 + 2] = __float2half_rn(__expf(LOG16 - f.z * inv_eps));
            dst[q * 4 + 3] = __float2half_rn(__expf(LOG16 - f.w * inv_eps));
        }
    }
    __syncthreads();

    const int warp = tid >> 5, lane = tid & 31;
    const int rr = lane >> 2, cc = (lane & 3) << 1;

#pragma unroll
    for (int p = 0; p < 2; ++p) {
        const int t = warp * 2 + p;          // 0..15
        const int i = t >> 2, j = t & 3;

        {   // K tile: rows = C rows, k = C cols
            const __half* b = sE + (i * 16 + rr) * 72 + (j * 16 + cc);
            unsigned r0 = *(const unsigned*)(b);
            unsigned r1 = *(const unsigned*)(b + 8 * 72);
            unsigned r2 = *(const unsigned*)(b + 8);
            unsigned r3 = *(const unsigned*)(b + 8 * 72 + 8);
            size_t tileK = ((size_t)((by >> 4) + i) * NTILES) + (bx >> 4) + j;
            ((uint4*)g_K)[tileK * 32 + lane] = make_uint4(r0, r1, r2, r3);
        }
        {   // KT tile: rows = C cols, k = C rows (transposed read)
            const __half* b = sE + (j * 16 + cc) * 72 + (i * 16 + rr);
            unsigned r0 = packh(b[0],          b[72]);
            unsigned r1 = packh(b[8],          b[72 + 8]);
            unsigned r2 = packh(b[8 * 72],     b[9 * 72]);
            unsigned r3 = packh(b[8 * 72 + 8], b[9 * 72 + 8]);
            size_t tileT = ((size_t)((bx >> 4) + i) * NTILES) + (by >> 4) + j;
            ((uint4*)g_KT)[tileT * 32 + lane] = make_uint4(r0, r1, r2, r3);
        }
    }
}

// ---------------------------------------------------------------------------
// Persistent tensor-core Sinkhorn. 256 blocks x 256 threads.
// Block rt = 16 rows x FULL 4096 cols; warp w covers k-tiles [w*32, w*32+32).
// Per tile: LDG.128 (K frag) + predicated LDG.64 (B frag) + HMMA.
// Epilogue: 8-warp reduce -> divide -> fp16 -> pack B-fragment tile rt.
// ---------------------------------------------------------------------------
__global__ void __launch_bounds__(NTHREADS, 2)
sinkhorn_persistent_kernel(const float* __restrict__ alpha,
                           const float* __restrict__ beta,
                           const float* __restrict__ epsp,
                           float* __restrict__ out) {
    __shared__ float  red[8 * 16 * 4];
    __shared__ __half yb[16 * 4];

    const int tid  = threadIdx.x;
    const int warp = tid >> 5;
    const int lane = tid & 31;
    const int rt   = blockIdx.x;
    const int row0 = rt * 16;
    const bool bl  = lane < 16;

    // init packed v = 1.0 (tile rt), then make visible grid-wide
    if (warp == 0 && bl)
        g_Bv[rt * 16 + lane] = make_uint2(0x3C003C00u, 0x3C003C00u);
    grid_sync();

    for (int it = 0; it < 2 * NITER; ++it) {
        const __half* M    = (it & 1) ? g_KT : g_K;
        const uint2*  Bin  = (it & 1) ? g_Bu : g_Bv;
        uint2*        Bout = (it & 1) ? g_Bv : g_Bu;
        float*        pdst = (it & 1) ? g_pv : g_pu;
        const float*  num  = (it & 1) ? beta : alpha;

        const uint4* kf = (const uint4*)M + ((size_t)rt * NTILES + warp * TPW) * 32 + lane;
        const uint2* bf = Bin + (warp * TPW) * 16 + lane;

        float dA0 = 0.f, dA1 = 0.f, dA2 = 0.f, dA3 = 0.f;
        float dB0 = 0.f, dB1 = 0.f, dB2 = 0.f, dB3 = 0.f;

        uint4 ka[4];
        uint2 ba[4];
#pragma unroll
        for (int q = 0; q < 4; ++q) {
            ka[q] = __ldcg(kf + q * 32);
            ba[q] = bl ? __ldcg(bf + q * 16) : make_uint2(0u, 0u);
        }

#pragma unroll
        for (int g = 0; g < TPW / 4; ++g) {      // 8 groups of 4 tiles
            uint4 nk[4];
            uint2 nb[4];
#pragma unroll
            for (int q = 0; q < 4; ++q) {
                if (g < TPW / 4 - 1) {
                    nk[q] = __ldcg(kf + ((g + 1) * 4 + q) * 32);
                    nb[q] = bl ? __ldcg(bf + ((g + 1) * 4 + q) * 16) : make_uint2(0u, 0u);
                } else { nk[q] = ka[q]; nb[q] = ba[q]; }
            }
#pragma unroll
            for (int q = 0; q < 4; ++q) {
                if (q & 1) {
                    asm volatile("mma.sync.aligned.m16n8k16.row.col.f32.f16.f16.f32 "
                                 "{%0,%1,%2,%3}, {%4,%5,%6,%7}, {%8,%9}, {%0,%1,%2,%3};"
                                 : "+f"(dB0), "+f"(dB1), "+f"(dB2), "+f"(dB3)
                                 : "r"(ka[q].x), "r"(ka[q].y), "r"(ka[q].z), "r"(ka[q].w),
                                   "r"(ba[q].x), "r"(ba[q].y));
                } else {
                    asm volatile("mma.sync.aligned.m16n8k16.row.col.f32.f16.f16.f32 "
                                 "{%0,%1,%2,%3}, {%4,%5,%6,%7}, {%8,%9}, {%0,%1,%2,%3};"
                                 : "+f"(dA0), "+f"(dA1), "+f"(dA2), "+f"(dA3)
                                 : "r"(ka[q].x), "r"(ka[q].y), "r"(ka[q].z), "r"(ka[q].w),
                                   "r"(ba[q].x), "r"(ba[q].y));
                }
            }
#pragma unroll
            for (int q = 0; q < 4; ++q) { ka[q] = nk[q]; ba[q] = nb[q]; }
        }

        const float d0 = dA0 + dB0, d1 = dA1 + dB1;
        const float d2 = dA2 + dB2, d3 = dA3 + dB3;

        // ---- epilogue: C fragments (cols 0-3 useful) -> smem -> reduce ----
        if ((lane & 3) < 2) {
            const int c = 2 * (lane & 3);
            const int r = lane >> 2;
            red[(warp * 16 + r) * 4 + c]         = d0;
            red[(warp * 16 + r) * 4 + c + 1]     = d1;
            red[(warp * 16 + r + 8) * 4 + c]     = d2;
            red[(warp * 16 + r + 8) * 4 + c + 1] = d3;
        }
        __syncthreads();
        if (tid < 64) {
            const int row = tid >> 2, c = tid & 3;
            float p = 0.f;
#pragma unroll
            for (int w = 0; w < 8; ++w)
                p += red[(w * 16 + row) * 4 + c];
            __stcg(pdst + (size_t)(row0 + row) * 4 + c, p);
            float y = __fdividef(F_SCALE * __ldg(num + (size_t)c * N + row0 + row), p);
            yb[row * 4 + c] = __float2half_rn(y);
        }
        __syncthreads();
        // pack tile rt of the next B operand (lanes 0-15; n>=4 implicit zero)
        if (warp == 0 && bl) {
            const int n = lane >> 2, k0 = (lane & 3) * 2;
            uint2 o;
            o.x = packh(yb[k0 * 4 + n],       yb[(k0 + 1) * 4 + n]);
            o.y = packh(yb[(k0 + 8) * 4 + n], yb[(k0 + 9) * 4 + n]);
            __stcg(Bout + rt * 16 + lane, o);
        }
        grid_sync();
    }

    // ---- finalize:  f = eps*(log a - log p_u + log16)
    //                 g = eps*(log b - log p_v + log 2^20)
    int n = blockIdx.x * NTHREADS + tid;
    if (n < N) {
        const float eps = *epsp;
        float4 pu = __ldcg((const float4*)g_pu + n);
        float4 pv = __ldcg((const float4*)g_pv + n);
        out[0 * N + n] = eps * (logf(alpha[0 * N + n]) - logf(pu.x) + LOG16);
        out[1 * N + n] = eps * (logf(alpha[1 * N + n]) - logf(pu.y) + LOG16);
        out[2 * N + n] = eps * (logf(alpha[2 * N + n]) - logf(pu.z) + LOG16);
        out[3 * N + n] = eps * (logf(alpha[3 * N + n]) - logf(pu.w) + LOG16);
        float* og = out + 4 * N;
        og[0 * N + n] = eps * (logf(beta[0 * N + n]) - logf(pv.x) + LOG_CU);
        og[1 * N + n] = eps * (logf(beta[1 * N + n]) - logf(pv.y) + LOG_CU);
        og[2 * N + n] = eps * (logf(beta[2 * N + n]) - logf(pv.z) + LOG_CU);
        og[3 * N + n] = eps * (logf(beta[3 * N + n]) - logf(pv.w) + LOG_CU);
    }
}

// ---------------------------------------------------------------------------
extern "C" void kernel_launch(void* const* d_in, const int* in_sizes, int n_in,
                              void* d_out, int out_size) {
    const float* alpha = (const float*)d_in[0];
    const float* beta  = (const float*)d_in[1];
    const float* C     = (const float*)d_in[2];
    const float* eps   = (const float*)d_in[3];
    float* out = (float*)d_out;

    frag_pack_kernel<<<dim3(64, 64), 256>>>(C, eps);
    sinkhorn_persistent_kernel<<<NBLOCKS, NTHREADS>>>(alpha, beta, eps, out);
}